// round 3
// baseline (speedup 1.0000x reference)
#include <cuda_runtime.h>

// ConvGRU cell, register-blocked: each thread computes 4 pixels x 16 output
// channels, so each 16B constant weight load feeds 8 FFMA2 (fma:LDC = 2:1).
// Input tiles staged in dynamic shared memory as [c][px] rows (float4 access).
// Weights transposed into __constant__ memory by a prep kernel.

#define HW 65536        // 256*256
#define NB 8

typedef unsigned long long ull;

__constant__ __align__(16) float cAll[7 * 1024 + 4 * 32];
__device__   __align__(16) float g_stage[7 * 1024 + 4 * 32];

__device__ __forceinline__ ull pack2(float a, float b) {
    ull r;
    asm("mov.b64 %0, {%1, %2};" : "=l"(r) : "f"(a), "f"(b));
    return r;
}
__device__ __forceinline__ void unpack2(ull v, float& a, float& b) {
    asm("mov.b64 {%0, %1}, %2;" : "=f"(a), "=f"(b) : "l"(v));
}
__device__ __forceinline__ void ffma2(ull& d, ull a, ull b) {
    asm("fma.rn.f32x2 %0, %1, %2, %3;" : "=l"(d) : "l"(a), "l"(b), "l"(d));
}
__device__ __forceinline__ float sigmoidf_(float a) {
    a = fminf(fmaxf(a, -30.f), 30.f);
    float e = __expf(-a);
    return __fdividef(1.f, 1.f + e);
}
__device__ __forceinline__ float tanhf_(float a) {
    a = fminf(fmaxf(a, -15.f), 15.f);
    float e = __expf(-2.f * a);
    return (1.f - e) * __fdividef(1.f, 1.f + e);
}

__global__ void prep_kernel(
    const float* __restrict__ w_xz, const float* __restrict__ w_hz,
    const float* __restrict__ w_xr, const float* __restrict__ w_hr,
    const float* __restrict__ w_c,  const float* __restrict__ w_u,
    const float* __restrict__ w_o,
    const float* __restrict__ b_xz, const float* __restrict__ b_hz,
    const float* __restrict__ b_xr, const float* __restrict__ b_hr,
    const float* __restrict__ b_c,  const float* __restrict__ b_u,
    const float* __restrict__ b_o)
{
    int t = threadIdx.x;               // 1024 threads
    int o = t & 31, c = t >> 5;
    g_stage[0 * 1024 + c * 32 + o] = w_xz[o * 32 + c];
    g_stage[1 * 1024 + c * 32 + o] = w_hz[o * 32 + c];
    g_stage[2 * 1024 + c * 32 + o] = w_xr[o * 32 + c];
    g_stage[3 * 1024 + c * 32 + o] = w_hr[o * 32 + c];
    g_stage[4 * 1024 + c * 32 + o] = w_c [o * 32 + c];
    g_stage[5 * 1024 + c * 32 + o] = w_u [o * 32 + c];
    g_stage[6 * 1024 + c * 32 + o] = w_o [o * 32 + c];
    if (t < 32) {
        g_stage[7168 +  0 + t] = b_xz[t] + b_hz[t];   // bz
        g_stage[7168 + 32 + t] = b_xr[t] + b_hr[t];   // br
        g_stage[7168 + 64 + t] = b_c[t]  + b_u[t];    // bc
        g_stage[7168 + 96 + t] = b_o[t];              // by
    }
}

// acc[px 0..3][opair 0..7] += W_m1[c][o]*in1[c][px] + W_m2[c][o]*in2[c][px]
// in1/in2 are smem tiles: float [32][256], row = channel.
#define SWEEP2(acc, m1, in1, m2, in2)                                          \
    _Pragma("unroll")                                                          \
    for (int c = 0; c < 32; c++) {                                             \
        float4 v1 = ((const float4*)&(in1)[c * 256])[pg];                      \
        float4 v2 = ((const float4*)&(in2)[c * 256])[pg];                      \
        ull d1[4] = { pack2(v1.x, v1.x), pack2(v1.y, v1.y),                    \
                      pack2(v1.z, v1.z), pack2(v1.w, v1.w) };                  \
        ull d2[4] = { pack2(v2.x, v2.x), pack2(v2.y, v2.y),                    \
                      pack2(v2.z, v2.z), pack2(v2.w, v2.w) };                  \
        const ulonglong2* w1 = (const ulonglong2*)&cAll[(m1) * 1024 + c * 32 + oh16]; \
        const ulonglong2* w2 = (const ulonglong2*)&cAll[(m2) * 1024 + c * 32 + oh16]; \
        _Pragma("unroll")                                                      \
        for (int q = 0; q < 4; q++) {                                          \
            ulonglong2 wa = w1[q];                                             \
            ulonglong2 wb = w2[q];                                             \
            _Pragma("unroll")                                                  \
            for (int i = 0; i < 4; i++) {                                      \
                ffma2((acc)[i][2 * q],     wa.x, d1[i]);                       \
                ffma2((acc)[i][2 * q],     wb.x, d2[i]);                       \
                ffma2((acc)[i][2 * q + 1], wa.y, d1[i]);                       \
                ffma2((acc)[i][2 * q + 1], wb.y, d2[i]);                       \
            }                                                                  \
        }                                                                      \
    }

#define SWEEP1(acc, m1, in1)                                                   \
    _Pragma("unroll")                                                          \
    for (int c = 0; c < 32; c++) {                                             \
        float4 v1 = ((const float4*)&(in1)[c * 256])[pg];                      \
        ull d1[4] = { pack2(v1.x, v1.x), pack2(v1.y, v1.y),                    \
                      pack2(v1.z, v1.z), pack2(v1.w, v1.w) };                  \
        const ulonglong2* w1 = (const ulonglong2*)&cAll[(m1) * 1024 + c * 32 + oh16]; \
        _Pragma("unroll")                                                      \
        for (int q = 0; q < 4; q++) {                                          \
            ulonglong2 wa = w1[q];                                             \
            _Pragma("unroll")                                                  \
            for (int i = 0; i < 4; i++) {                                      \
                ffma2((acc)[i][2 * q],     wa.x, d1[i]);                       \
                ffma2((acc)[i][2 * q + 1], wa.y, d1[i]);                       \
            }                                                                  \
        }                                                                      \
    }

#define INIT_ACC(acc, boff)                                                    \
    _Pragma("unroll")                                                          \
    for (int q = 0; q < 8; q++) {                                              \
        ull bb = pack2(cAll[7168 + (boff) + oh16 + 2 * q],                     \
                       cAll[7168 + (boff) + oh16 + 2 * q + 1]);                \
        _Pragma("unroll")                                                      \
        for (int i = 0; i < 4; i++) (acc)[i][q] = bb;                          \
    }

__global__ void __launch_bounds__(128, 2) gru_fused_kernel(
    const float* __restrict__ x, const float* __restrict__ h,
    float* __restrict__ out)
{
    extern __shared__ float smem[];
    float* xs = smem;               // [32][256]
    float* hs = smem + 8192;        // [32][256]
    float* ts = smem + 16384;       // [32][256]   rv, then ht

    const int tid  = threadIdx.x;
    const int pg   = tid & 63;          // pixel group (4 px each)
    const int oh16 = (tid >> 6) * 16;   // output-half base channel

    const int gp0 = blockIdx.x * 256;   // 2048 blocks cover 524288 px
    const int b   = gp0 >> 16;
    const int p0  = gp0 & 65535;

    // ---- stage input tiles: xs/hs[c][px] ----
    {
        const float4* x4 = (const float4*)(x + (b * 32) * HW + p0);
        const float4* h4 = (const float4*)(h + (b * 32) * HW + p0);
#pragma unroll
        for (int k = 0; k < 16; k++) {
            int idx = tid + k * 128;        // 0..2047
            int c = idx >> 6, j = idx & 63;
            ((float4*)&xs[c * 256])[j] = x4[c * (HW / 4) + j];
            ((float4*)&hs[c * 256])[j] = h4[c * (HW / 4) + j];
        }
    }
    __syncthreads();

    // ---- r gate: racc = Wxr*x + Whr*h + br ----
    ull racc[4][8];
    INIT_ACC(racc, 32)
    SWEEP2(racc, 2, xs, 3, hs)

    // rv = sigmoid(r) * h -> ts
#pragma unroll
    for (int q = 0; q < 8; q++) {
        int o0 = oh16 + 2 * q, o1 = o0 + 1;
        float4 h0 = ((const float4*)&hs[o0 * 256])[pg];
        float4 h1 = ((const float4*)&hs[o1 * 256])[pg];
        const float* h0f = (const float*)&h0;
        const float* h1f = (const float*)&h1;
        float r0[4], r1[4];
#pragma unroll
        for (int i = 0; i < 4; i++) {
            float a0, a1;
            unpack2(racc[i][q], a0, a1);
            r0[i] = sigmoidf_(a0) * h0f[i];
            r1[i] = sigmoidf_(a1) * h1f[i];
        }
        ((float4*)&ts[o0 * 256])[pg] = make_float4(r0[0], r0[1], r0[2], r0[3]);
        ((float4*)&ts[o1 * 256])[pg] = make_float4(r1[0], r1[1], r1[2], r1[3]);
    }
    __syncthreads();

    // ---- candidate pre-activation: cacc = Wc*x + Wu*rv + bc ----
    ull cacc[4][8];
    INIT_ACC(cacc, 64)
    SWEEP2(cacc, 4, xs, 5, ts)

    // ---- z gate: zacc = Wxz*x + Whz*h + bz  (reads xs/hs only) ----
    ull zacc[4][8];
    INIT_ACC(zacc, 0)
    SWEEP2(zacc, 0, xs, 1, hs)
    __syncthreads();    // everyone done reading ts=rv; safe to overwrite

    // ---- blend: ht = h + sigmoid(z)*(tanh(c) - h); write ts + gmem ----
    float* houtb = out + NB * 32 * HW + (b * 32) * HW + p0;
#pragma unroll
    for (int q = 0; q < 8; q++) {
        int o0 = oh16 + 2 * q, o1 = o0 + 1;
        float4 h0 = ((const float4*)&hs[o0 * 256])[pg];
        float4 h1 = ((const float4*)&hs[o1 * 256])[pg];
        const float* h0f = (const float*)&h0;
        const float* h1f = (const float*)&h1;
        float t0[4], t1[4];
#pragma unroll
        for (int i = 0; i < 4; i++) {
            float c0, c1, z0, z1;
            unpack2(cacc[i][q], c0, c1);
            unpack2(zacc[i][q], z0, z1);
            float hh0 = tanhf_(c0), hh1 = tanhf_(c1);
            float zf0 = sigmoidf_(z0), zf1 = sigmoidf_(z1);
            t0[i] = fmaf(zf0, hh0 - h0f[i], h0f[i]);
            t1[i] = fmaf(zf1, hh1 - h1f[i], h1f[i]);
        }
        float4 v0 = make_float4(t0[0], t0[1], t0[2], t0[3]);
        float4 v1 = make_float4(t1[0], t1[1], t1[2], t1[3]);
        ((float4*)&ts[o0 * 256])[pg] = v0;
        ((float4*)&ts[o1 * 256])[pg] = v1;
        ((float4*)(houtb + o0 * HW))[pg] = v0;
        ((float4*)(houtb + o1 * HW))[pg] = v1;
    }
    __syncthreads();

    // ---- output projection: y = Wo*ht + by ----
    ull yacc[4][8];
    INIT_ACC(yacc, 96)
    SWEEP1(yacc, 6, ts)

    float* youtb = out + (b * 32) * HW + p0;
#pragma unroll
    for (int q = 0; q < 8; q++) {
        int o0 = oh16 + 2 * q, o1 = o0 + 1;
        float y0[4], y1[4];
#pragma unroll
        for (int i = 0; i < 4; i++) unpack2(yacc[i][q], y0[i], y1[i]);
        ((float4*)(youtb + o0 * HW))[pg] = make_float4(y0[0], y0[1], y0[2], y0[3]);
        ((float4*)(youtb + o1 * HW))[pg] = make_float4(y1[0], y1[1], y1[2], y1[3]);
    }
}

extern "C" void kernel_launch(void* const* d_in, const int* in_sizes, int n_in,
                              void* d_out, int out_size) {
    const float* x    = (const float*)d_in[0];
    const float* h    = (const float*)d_in[1];
    const float* w_xz = (const float*)d_in[2];
    const float* b_xz = (const float*)d_in[3];
    const float* w_hz = (const float*)d_in[4];
    const float* b_hz = (const float*)d_in[5];
    const float* w_xr = (const float*)d_in[6];
    const float* b_xr = (const float*)d_in[7];
    const float* w_hr = (const float*)d_in[8];
    const float* b_hr = (const float*)d_in[9];
    const float* w_c  = (const float*)d_in[10];
    const float* b_c  = (const float*)d_in[11];
    const float* w_u  = (const float*)d_in[12];
    const float* b_u  = (const float*)d_in[13];
    const float* w_o  = (const float*)d_in[14];
    const float* b_o  = (const float*)d_in[15];
    float* out = (float*)d_out;

    prep_kernel<<<1, 1024>>>(w_xz, w_hz, w_xr, w_hr, w_c, w_u, w_o,
                             b_xz, b_hz, b_xr, b_hr, b_c, b_u, b_o);

    void *csym = nullptr, *gsym = nullptr;
    cudaGetSymbolAddress(&csym, cAll);
    cudaGetSymbolAddress(&gsym, g_stage);
    cudaMemcpyAsync(csym, gsym, sizeof(float) * (7 * 1024 + 4 * 32),
                    cudaMemcpyDeviceToDevice);

    cudaFuncSetAttribute(gru_fused_kernel,
                         cudaFuncAttributeMaxDynamicSharedMemorySize, 98304);
    gru_fused_kernel<<<2048, 128, 98304>>>(x, h, out);
}